// round 1
// baseline (speedup 1.0000x reference)
#include <cuda_runtime.h>
#include <cstdint>
#include <cstddef>

#define B_ 4
#define H_ 16
#define S_ 2048
#define D_ 64
#define BM 128
#define BN 128
#define NT 256
#define QP 132   // Qs/Ks row stride (floats)
#define VP 68    // Vs row stride
#define PP 132   // Ps row stride
#define SMEM_FLOATS (D_*QP + D_*QP + BN*VP + BM*PP)

typedef unsigned long long u64;

// ---- packed fp32x2 helpers (sm_103a dual-rate fp32) ----
__device__ __forceinline__ u64 pk2(float lo, float hi) {
  u64 r; asm("mov.b64 %0, {%1, %2};" : "=l"(r) : "f"(lo), "f"(hi)); return r;
}
__device__ __forceinline__ u64 dup2(float x) {
  u64 r; asm("mov.b64 %0, {%1, %1};" : "=l"(r) : "f"(x)); return r;
}
__device__ __forceinline__ void upk2(u64 v, float& lo, float& hi) {
  asm("mov.b64 {%0, %1}, %2;" : "=f"(lo), "=f"(hi) : "l"(v));
}
__device__ __forceinline__ u64 fma2(u64 a, u64 b, u64 c) {
  u64 r; asm("fma.rn.f32x2 %0, %1, %2, %3;" : "=l"(r) : "l"(a), "l"(b), "l"(c)); return r;
}
__device__ __forceinline__ u64 mul2(u64 a, u64 b) {
  u64 r; asm("mul.rn.f32x2 %0, %1, %2;" : "=l"(r) : "l"(a), "l"(b)); return r;
}

__global__ void __launch_bounds__(NT, 1)
attn_fused_kernel(const float* __restrict__ q, const float* __restrict__ k,
                  const float* __restrict__ v, const int* __restrict__ mask,
                  float* __restrict__ out_o, float* __restrict__ out_s)
{
  extern __shared__ float sm[];
  float* Qs = sm;                 // [D_][QP]  (d-major: Qs[d][i] = q[i][d])
  float* Ks = Qs + D_ * QP;       // [D_][QP]  (Ks[d][j] = k[d][j])
  float* Vs = Ks + D_ * QP;       // [BN][VP]  (Vs[jj][d])
  float* Ps = Vs + BN * VP;       // [BM][PP]  (Ps[r][jj], natural layout)

  const int h  = blockIdx.x;
  const int it = blockIdx.y;
  const int b  = blockIdx.z;
  const int i0 = it * BM;
  const int bh = b * H_ + h;

  const int tid = threadIdx.x;
  const int tx = tid & 15;
  const int ty = tid >> 4;
  const int r0 = ty * 8;   // 8 rows per thread
  const int c0 = tx * 8;   // 8 score cols per thread
  const int d0 = tx * 4;   // 4 output cols per thread

  const float* qbase = q + ((size_t)bh * S_ + i0) * D_;
  const float* kbase = k + (size_t)bh * D_ * S_;
  const float* vbase = v + (size_t)bh * S_ * D_;

  // ---- load Q tile transposed into smem (once) ----
  #pragma unroll
  for (int rep = 0; rep < 8; rep++) {
    int idx = tid + rep * NT;           // 0..2047 (2048 float4)
    int ii  = idx >> 4;                 // 0..127
    int c4  = (idx & 15) * 4;           // 0..60
    float4 qv = *(const float4*)(qbase + (size_t)ii * D_ + c4);
    Qs[(c4 + 0) * QP + ii] = qv.x;
    Qs[(c4 + 1) * QP + ii] = qv.y;
    Qs[(c4 + 2) * QP + ii] = qv.z;
    Qs[(c4 + 3) * QP + ii] = qv.w;
  }

  u64 Oacc[8][2];
  float mrow[8], lrow[8];
  #pragma unroll
  for (int rr = 0; rr < 8; rr++) {
    Oacc[rr][0] = 0ull; Oacc[rr][1] = 0ull;
    mrow[rr] = -1e30f; lrow[rr] = 0.f;
  }

  for (int jt = 0; jt < S_ / BN; jt++) {
    const int j0 = jt * BN;
    __syncthreads();
    // ---- load K tile [D_ x BN] ----
    #pragma unroll
    for (int rep = 0; rep < 8; rep++) {
      int idx = tid + rep * NT;
      int dd  = idx >> 5;               // 0..63
      int c4  = (idx & 31) * 4;         // 0..124
      float4 kv = *(const float4*)(kbase + (size_t)dd * S_ + j0 + c4);
      *(float4*)&Ks[dd * QP + c4] = kv;
    }
    // ---- load V tile [BN x D_] ----
    #pragma unroll
    for (int rep = 0; rep < 8; rep++) {
      int idx = tid + rep * NT;
      int jj  = idx >> 4;               // 0..127
      int c4  = (idx & 15) * 4;         // 0..60
      float4 vv = *(const float4*)(vbase + (size_t)(j0 + jj) * D_ + c4);
      *(float4*)&Vs[jj * VP + c4] = vv;
    }
    __syncthreads();

    // ---- S tile: 8x8 per thread, packed f32x2 accumulators ----
    u64 acc[8][4];
    #pragma unroll
    for (int rr = 0; rr < 8; rr++)
      #pragma unroll
      for (int cc = 0; cc < 4; cc++) acc[rr][cc] = 0ull;

    #pragma unroll 16
    for (int kk = 0; kk < D_; kk++) {
      float4 qa = *(float4*)&Qs[kk * QP + r0];
      float4 qb = *(float4*)&Qs[kk * QP + r0 + 4];
      float4 ka = *(float4*)&Ks[kk * QP + c0];
      float4 kb = *(float4*)&Ks[kk * QP + c0 + 4];
      u64 b0 = pk2(ka.x, ka.y), b1 = pk2(ka.z, ka.w);
      u64 b2 = pk2(kb.x, kb.y), b3 = pk2(kb.z, kb.w);
      float av[8] = {qa.x, qa.y, qa.z, qa.w, qb.x, qb.y, qb.z, qb.w};
      #pragma unroll
      for (int rr = 0; rr < 8; rr++) {
        u64 ad = dup2(av[rr]);
        acc[rr][0] = fma2(ad, b0, acc[rr][0]);
        acc[rr][1] = fma2(ad, b1, acc[rr][1]);
        acc[rr][2] = fma2(ad, b2, acc[rr][2]);
        acc[rr][3] = fma2(ad, b3, acc[rr][3]);
      }
    }

    // ---- epilogue: unpack, scale, mask, store score ----
    float p[8][8];
    #pragma unroll
    for (int rr = 0; rr < 8; rr++) {
      upk2(acc[rr][0], p[rr][0], p[rr][1]);
      upk2(acc[rr][1], p[rr][2], p[rr][3]);
      upk2(acc[rr][2], p[rr][4], p[rr][5]);
      upk2(acc[rr][3], p[rr][6], p[rr][7]);
    }
    #pragma unroll
    for (int rr = 0; rr < 8; rr++) {
      int gi = i0 + r0 + rr;
      const int* mp = mask + ((size_t)b * S_ + gi) * S_ + j0 + c0;
      int4 m0 = *(const int4*)(mp);
      int4 m1 = *(const int4*)(mp + 4);
      p[rr][0] = m0.x ? p[rr][0] * 0.125f : -1e10f;
      p[rr][1] = m0.y ? p[rr][1] * 0.125f : -1e10f;
      p[rr][2] = m0.z ? p[rr][2] * 0.125f : -1e10f;
      p[rr][3] = m0.w ? p[rr][3] * 0.125f : -1e10f;
      p[rr][4] = m1.x ? p[rr][4] * 0.125f : -1e10f;
      p[rr][5] = m1.y ? p[rr][5] * 0.125f : -1e10f;
      p[rr][6] = m1.z ? p[rr][6] * 0.125f : -1e10f;
      p[rr][7] = m1.w ? p[rr][7] * 0.125f : -1e10f;
      if (out_s) {
        float* sp = out_s + ((size_t)bh * S_ + gi) * S_ + j0 + c0;
        float4 s0 = make_float4(p[rr][0], p[rr][1], p[rr][2], p[rr][3]);
        float4 s1 = make_float4(p[rr][4], p[rr][5], p[rr][6], p[rr][7]);
        *(float4*)sp = s0;
        *(float4*)(sp + 4) = s1;
      }
    }

    // ---- online softmax update + write P to smem ----
    #pragma unroll
    for (int rr = 0; rr < 8; rr++) {
      float rmx = p[rr][0];
      #pragma unroll
      for (int cc = 1; cc < 8; cc++) rmx = fmaxf(rmx, p[rr][cc]);
      #pragma unroll
      for (int o = 8; o > 0; o >>= 1)
        rmx = fmaxf(rmx, __shfl_xor_sync(0xffffffffu, rmx, o, 16));
      float mn = fmaxf(mrow[rr], rmx);
      float fs = __expf(mrow[rr] - mn);
      mrow[rr] = mn;
      float rs = 0.f;
      #pragma unroll
      for (int cc = 0; cc < 8; cc++) {
        float e = __expf(p[rr][cc] - mn);
        p[rr][cc] = e;
        rs += e;
      }
      #pragma unroll
      for (int o = 8; o > 0; o >>= 1)
        rs += __shfl_xor_sync(0xffffffffu, rs, o, 16);
      lrow[rr] = lrow[rr] * fs + rs;
      u64 fd = dup2(fs);
      Oacc[rr][0] = mul2(Oacc[rr][0], fd);
      Oacc[rr][1] = mul2(Oacc[rr][1], fd);
      *(float4*)&Ps[(r0 + rr) * PP + c0]     = make_float4(p[rr][0], p[rr][1], p[rr][2], p[rr][3]);
      *(float4*)&Ps[(r0 + rr) * PP + c0 + 4] = make_float4(p[rr][4], p[rr][5], p[rr][6], p[rr][7]);
    }
    __syncthreads();

    // ---- PV accumulate: O[8 rows][4 cols] ----
    #pragma unroll 4
    for (int jc = 0; jc < BN / 4; jc++) {
      float4 pr[8];
      #pragma unroll
      for (int rr = 0; rr < 8; rr++)
        pr[rr] = *(float4*)&Ps[(r0 + rr) * PP + jc * 4];
      #pragma unroll
      for (int qq = 0; qq < 4; qq++) {
        int jj = jc * 4 + qq;
        float4 vv = *(float4*)&Vs[jj * VP + d0];
        u64 vb0 = pk2(vv.x, vv.y), vb1 = pk2(vv.z, vv.w);
        #pragma unroll
        for (int rr = 0; rr < 8; rr++) {
          float a = (qq == 0) ? pr[rr].x : (qq == 1) ? pr[rr].y
                  : (qq == 2) ? pr[rr].z : pr[rr].w;
          u64 ad = dup2(a);
          Oacc[rr][0] = fma2(ad, vb0, Oacc[rr][0]);
          Oacc[rr][1] = fma2(ad, vb1, Oacc[rr][1]);
        }
      }
    }
  }

  // ---- finalize output ----
  if (out_o) {
    #pragma unroll
    for (int rr = 0; rr < 8; rr++) {
      float inv = 1.0f / lrow[rr];
      float o0, o1, o2, o3;
      upk2(Oacc[rr][0], o0, o1);
      upk2(Oacc[rr][1], o2, o3);
      float4 ov = make_float4(o0 * inv, o1 * inv, o2 * inv, o3 * inv);
      *(float4*)(out_o + ((size_t)bh * S_ + (i0 + r0 + rr)) * D_ + d0) = ov;
    }
  }
}

extern "C" void kernel_launch(void* const* d_in, const int* in_sizes, int n_in,
                              void* d_out, int out_size) {
  const float* q = (const float*)d_in[0];
  const float* k = (const float*)d_in[1];
  const float* v = (const float*)d_in[2];
  const int* mask = (const int*)d_in[3];

  const size_t nO = (size_t)B_ * H_ * S_ * D_;   // 8388608
  const size_t nS = (size_t)B_ * H_ * S_ * S_;   // 268435456

  float* base = (float*)d_out;
  float* out_o = nullptr;
  float* out_s = nullptr;
  if ((size_t)out_size == nO + nS) { out_o = base; out_s = base + nO; }
  else if ((size_t)out_size == nS) { out_s = base; }
  else                             { out_o = base; }

  const int smem_bytes = SMEM_FLOATS * (int)sizeof(float);  // ~166 KB
  cudaFuncSetAttribute(attn_fused_kernel,
                       cudaFuncAttributeMaxDynamicSharedMemorySize, smem_bytes);

  dim3 grid(H_, S_ / BM, B_);   // h fastest -> mask tiles shared across heads in L2
  attn_fused_kernel<<<grid, NT, smem_bytes>>>(q, k, v, mask, out_o, out_s);
}

// round 3
// speedup vs baseline: 1.8211x; 1.8211x over previous
#include <cuda_runtime.h>
#include <cuda_fp16.h>
#include <cstdint>
#include <cstddef>

#define B_ 4
#define H_ 16
#define S_ 2048
#define D_ 64
#define BM 128
#define NT 512

// ---- smem byte offsets ----
#define SM_QHI 0        // [128][64] f16, 128B rows, SWZ1 (16KB)
#define SM_QLO 16384
#define SM_KHI 32768    // [64][128] f16, 256B rows, SWZ2 (16KB)
#define SM_KLO 49152
#define SM_VHI 65536    // [128][64] f16, 128B rows, SWZ1 (16KB)
#define SM_VLO 81920
#define SM_PHI 98304    // [128][128] f16, 256B rows, SWZ2 (32KB)
#define SM_PLO 131072
#define SM_LRED 163840  // 4*128 f32
#define SM_TOTAL 165888

#define SWZ1(x) ((x) ^ (((x) >> 3) & 0x70))
#define SWZ2(x) ((x) ^ (((x) >> 4) & 0x70))
#define LOG2E 1.4426950408889634f

__device__ __forceinline__ uint32_t s2u(const void* p) {
  uint32_t a;
  asm("{ .reg .u64 t; cvta.to.shared.u64 t, %1; cvt.u32.u64 %0, t; }" : "=r"(a) : "l"(p));
  return a;
}

__device__ __forceinline__ void ldsm4(uint32_t r[4], uint32_t a) {
  asm volatile("ldmatrix.sync.aligned.m8n8.x4.shared.b16 {%0,%1,%2,%3}, [%4];"
               : "=r"(r[0]), "=r"(r[1]), "=r"(r[2]), "=r"(r[3]) : "r"(a));
}
__device__ __forceinline__ void ldsm4t(uint32_t r[4], uint32_t a) {
  asm volatile("ldmatrix.sync.aligned.m8n8.x4.trans.shared.b16 {%0,%1,%2,%3}, [%4];"
               : "=r"(r[0]), "=r"(r[1]), "=r"(r[2]), "=r"(r[3]) : "r"(a));
}
__device__ __forceinline__ void mma16816(float c[4], const uint32_t a[4], const uint32_t b[2]) {
  asm volatile(
    "mma.sync.aligned.m16n8k16.row.col.f32.f16.f16.f32 "
    "{%0,%1,%2,%3}, {%4,%5,%6,%7}, {%8,%9}, {%0,%1,%2,%3};"
    : "+f"(c[0]), "+f"(c[1]), "+f"(c[2]), "+f"(c[3])
    : "r"(a[0]), "r"(a[1]), "r"(a[2]), "r"(a[3]), "r"(b[0]), "r"(b[1]));
}
__device__ __forceinline__ uint32_t packh2(float x, float y) {
  __half2 hh = __floats2half2_rn(x, y);
  return *reinterpret_cast<uint32_t*>(&hh);
}
__device__ __forceinline__ float hround(float x) {
  return __half2float(__float2half_rn(x));
}

__global__ void __launch_bounds__(NT, 1)
attn_mma_kernel(const float* __restrict__ q, const float* __restrict__ k,
                const float* __restrict__ v, const int* __restrict__ mask,
                float* __restrict__ out_o, float* __restrict__ out_s)
{
  extern __shared__ char smc[];
  const uint32_t sb = s2u(smc);

  const int h = blockIdx.x, it = blockIdx.y, b = blockIdx.z;
  const int i0 = it * BM;
  const int bh = b * H_ + h;

  const int tid = threadIdx.x;
  const int lane = tid & 31;
  const int w = tid >> 5;
  const int wm = w & 3;      // S/O row block: 32*wm
  const int wn = w >> 2;     // S col block: 32*wn ; O col block: 16*wn

  const float* qbase = q + ((size_t)bh * S_ + i0) * D_;
  const float* kbase = k + (size_t)bh * D_ * S_;
  const float* vbase = v + (size_t)bh * S_ * D_;

  // ---- Q load + fp16 split (resident all kernel) ----
  #pragma unroll
  for (int rep = 0; rep < 4; rep++) {
    int idx = tid + rep * NT;        // 2048 float4
    int ii = idx >> 4;
    int d4 = (idx & 15) * 4;
    float4 qv = *(const float4*)(qbase + (size_t)ii * D_ + d4);
    float hx = hround(qv.x), hy = hround(qv.y), hz = hround(qv.z), hw = hround(qv.w);
    uint32_t off = SWZ1(ii * 128 + d4 * 2);
    *(uint2*)(smc + SM_QHI + off) = make_uint2(packh2(hx, hy), packh2(hz, hw));
    *(uint2*)(smc + SM_QLO + off) =
        make_uint2(packh2(qv.x - hx, qv.y - hy), packh2(qv.z - hz, qv.w - hw));
  }

  float oacc[2][2][4];
  #pragma unroll
  for (int t = 0; t < 2; t++)
    #pragma unroll
    for (int n = 0; n < 2; n++)
      #pragma unroll
      for (int r = 0; r < 4; r++) oacc[t][n][r] = 0.f;
  float lsum[2][2] = {{0.f, 0.f}, {0.f, 0.f}};

  for (int jt = 0; jt < S_ / 128; jt++) {
    const int j0 = jt * 128;
    __syncthreads();   // protect Ks/Vs/Ps from previous tile's readers

    // ---- K tile: gmem [d][j] -> Ks [64][128] f16 hi/lo ----
    #pragma unroll
    for (int rep = 0; rep < 4; rep++) {
      int idx = tid + rep * NT;
      int dd = idx >> 5;
      int j4 = (idx & 31) * 4;
      float4 kv = *(const float4*)(kbase + (size_t)dd * S_ + j0 + j4);
      float hx = hround(kv.x), hy = hround(kv.y), hz = hround(kv.z), hw = hround(kv.w);
      uint32_t off = SWZ2(dd * 256 + j4 * 2);
      *(uint2*)(smc + SM_KHI + off) = make_uint2(packh2(hx, hy), packh2(hz, hw));
      *(uint2*)(smc + SM_KLO + off) =
          make_uint2(packh2(kv.x - hx, kv.y - hy), packh2(kv.z - hz, kv.w - hw));
    }
    // ---- V tile: gmem [j][d] -> Vs [128][64] f16 hi/lo ----
    #pragma unroll
    for (int rep = 0; rep < 4; rep++) {
      int idx = tid + rep * NT;
      int jj = idx >> 4;
      int d4 = (idx & 15) * 4;
      float4 vv = *(const float4*)(vbase + (size_t)(j0 + jj) * D_ + d4);
      float hx = hround(vv.x), hy = hround(vv.y), hz = hround(vv.z), hw = hround(vv.w);
      uint32_t off = SWZ1(jj * 128 + d4 * 2);
      *(uint2*)(smc + SM_VHI + off) = make_uint2(packh2(hx, hy), packh2(hz, hw));
      *(uint2*)(smc + SM_VLO + off) =
          make_uint2(packh2(vv.x - hx, vv.y - hy), packh2(vv.z - hz, vv.w - hw));
    }
    __syncthreads();

    // ---- QK^T: warp computes S[32 x 32] at (32*wm, 32*wn) ----
    float sacc[2][4][4];
    #pragma unroll
    for (int t = 0; t < 2; t++)
      #pragma unroll
      for (int n = 0; n < 4; n++)
        #pragma unroll
        for (int r = 0; r < 4; r++) sacc[t][n][r] = 0.f;

    #pragma unroll
    for (int ks = 0; ks < 4; ks++) {
      uint32_t ahi[2][4], alo[2][4];
      #pragma unroll
      for (int t = 0; t < 2; t++) {
        uint32_t ra = SWZ1((wm * 32 + t * 16 + (lane & 15)) * 128 + ks * 32 + (lane >> 4) * 16);
        ldsm4(ahi[t], sb + SM_QHI + ra);
        ldsm4(alo[t], sb + SM_QLO + ra);
      }
      uint32_t bhi[4][2], blo[4][2];
      #pragma unroll
      for (int p = 0; p < 2; p++) {
        uint32_t rb = SWZ2((ks * 16 + (lane & 7) + ((lane >> 3) & 1) * 8) * 256 +
                           (wn * 32 + p * 16 + (lane >> 4) * 8) * 2);
        uint32_t r[4];
        ldsm4t(r, sb + SM_KHI + rb);
        bhi[2*p][0] = r[0]; bhi[2*p][1] = r[1]; bhi[2*p+1][0] = r[2]; bhi[2*p+1][1] = r[3];
        ldsm4t(r, sb + SM_KLO + rb);
        blo[2*p][0] = r[0]; blo[2*p][1] = r[1]; blo[2*p+1][0] = r[2]; blo[2*p+1][1] = r[3];
      }
      #pragma unroll
      for (int t = 0; t < 2; t++)
        #pragma unroll
        for (int n = 0; n < 4; n++) {
          mma16816(sacc[t][n], ahi[t], bhi[n]);
          mma16816(sacc[t][n], ahi[t], blo[n]);
          mma16816(sacc[t][n], alo[t], bhi[n]);
        }
    }

    // ---- epilogue: mask/scale, score STG, exp, split P -> smem ----
    #pragma unroll
    for (int t = 0; t < 2; t++) {
      #pragma unroll
      for (int n = 0; n < 4; n++) {
        int rl0 = wm * 32 + t * 16 + (lane >> 2);
        int rl1 = rl0 + 8;
        int cl  = wn * 32 + n * 8 + (lane & 3) * 2;
        int gr0 = i0 + rl0, gr1 = i0 + rl1, gc = j0 + cl;
        int2 m0 = *(const int2*)(mask + ((size_t)b * S_ + gr0) * S_ + gc);
        int2 m1 = *(const int2*)(mask + ((size_t)b * S_ + gr1) * S_ + gc);
        float s0 = m0.x ? sacc[t][n][0] * 0.125f : -1e10f;
        float s1 = m0.y ? sacc[t][n][1] * 0.125f : -1e10f;
        float s2 = m1.x ? sacc[t][n][2] * 0.125f : -1e10f;
        float s3 = m1.y ? sacc[t][n][3] * 0.125f : -1e10f;
        if (out_s) {
          *(float2*)(out_s + ((size_t)bh * S_ + gr0) * S_ + gc) = make_float2(s0, s1);
          *(float2*)(out_s + ((size_t)bh * S_ + gr1) * S_ + gc) = make_float2(s2, s3);
        }
        float p0 = exp2f(s0 * LOG2E);
        float p1 = exp2f(s1 * LOG2E);
        float p2 = exp2f(s2 * LOG2E);
        float p3 = exp2f(s3 * LOG2E);
        lsum[t][0] += p0 + p1;
        lsum[t][1] += p2 + p3;
        float h0 = hround(p0), h1 = hround(p1), h2 = hround(p2), h3 = hround(p3);
        uint32_t off0 = SWZ2(rl0 * 256 + cl * 2);
        uint32_t off1 = SWZ2(rl1 * 256 + cl * 2);
        *(uint32_t*)(smc + SM_PHI + off0) = packh2(h0, h1);
        *(uint32_t*)(smc + SM_PHI + off1) = packh2(h2, h3);
        *(uint32_t*)(smc + SM_PLO + off0) = packh2(p0 - h0, p1 - h1);
        *(uint32_t*)(smc + SM_PLO + off1) = packh2(p2 - h2, p3 - h3);
      }
    }
    __syncthreads();

    // ---- P V: warp computes O[32 x 16] at (32*wm, 16*wn), accum across tiles ----
    #pragma unroll
    for (int ks = 0; ks < 8; ks++) {
      uint32_t phi[2][4], plo[2][4];
      #pragma unroll
      for (int t = 0; t < 2; t++) {
        uint32_t ra = SWZ2((wm * 32 + t * 16 + (lane & 15)) * 256 + ks * 32 + (lane >> 4) * 16);
        ldsm4(phi[t], sb + SM_PHI + ra);
        ldsm4(plo[t], sb + SM_PLO + ra);
      }
      uint32_t vh[2][2], vl[2][2];
      {
        uint32_t rb = SWZ1((ks * 16 + (lane & 7) + ((lane >> 3) & 1) * 8) * 128 +
                           (wn * 16 + (lane >> 4) * 8) * 2);
        uint32_t r[4];
        ldsm4t(r, sb + SM_VHI + rb);
        vh[0][0] = r[0]; vh[0][1] = r[1]; vh[1][0] = r[2]; vh[1][1] = r[3];
        ldsm4t(r, sb + SM_VLO + rb);
        vl[0][0] = r[0]; vl[0][1] = r[1]; vl[1][0] = r[2]; vl[1][1] = r[3];
      }
      #pragma unroll
      for (int t = 0; t < 2; t++)
        #pragma unroll
        for (int n = 0; n < 2; n++) {
          mma16816(oacc[t][n], phi[t], vh[n]);
          mma16816(oacc[t][n], phi[t], vl[n]);
          mma16816(oacc[t][n], plo[t], vh[n]);
        }
    }
  }

  // ---- l reduction across cols: quad shuffle, then 4 wn warps via smem ----
  float* lred = (float*)(smc + SM_LRED);
  #pragma unroll
  for (int t = 0; t < 2; t++)
    #pragma unroll
    for (int hh = 0; hh < 2; hh++) {
      float vs = lsum[t][hh];
      vs += __shfl_xor_sync(0xffffffffu, vs, 1);
      vs += __shfl_xor_sync(0xffffffffu, vs, 2);
      lsum[t][hh] = vs;
    }
  __syncthreads();
  if ((lane & 3) == 0) {
    #pragma unroll
    for (int t = 0; t < 2; t++)
      #pragma unroll
      for (int hh = 0; hh < 2; hh++)
        lred[wn * 128 + wm * 32 + t * 16 + hh * 8 + (lane >> 2)] = lsum[t][hh];
  }
  __syncthreads();

  if (out_o) {
    #pragma unroll
    for (int t = 0; t < 2; t++) {
      #pragma unroll
      for (int hh = 0; hh < 2; hh++) {
        int rl = wm * 32 + t * 16 + hh * 8 + (lane >> 2);
        float lt = lred[rl] + lred[128 + rl] + lred[256 + rl] + lred[384 + rl];
        float inv = 1.0f / lt;
        int gr = i0 + rl;
        #pragma unroll
        for (int n = 0; n < 2; n++) {
          int gc = wn * 16 + n * 8 + (lane & 3) * 2;
          float2 ov = make_float2(oacc[t][n][2 * hh] * inv, oacc[t][n][2 * hh + 1] * inv);
          *(float2*)(out_o + ((size_t)bh * S_ + gr) * D_ + gc) = ov;
        }
      }
    }
  }
}

extern "C" void kernel_launch(void* const* d_in, const int* in_sizes, int n_in,
                              void* d_out, int out_size) {
  const float* q = (const float*)d_in[0];
  const float* k = (const float*)d_in[1];
  const float* v = (const float*)d_in[2];
  const int* mask = (const int*)d_in[3];

  const size_t nO = (size_t)B_ * H_ * S_ * D_;   // 8388608
  const size_t nS = (size_t)B_ * H_ * S_ * S_;   // 268435456

  float* base = (float*)d_out;
  float* out_o = nullptr;
  float* out_s = nullptr;
  if ((size_t)out_size == nO + nS) { out_o = base; out_s = base + nO; }
  else if ((size_t)out_size == nS) { out_s = base; }
  else                             { out_o = base; }

  cudaFuncSetAttribute(attn_mma_kernel,
                       cudaFuncAttributeMaxDynamicSharedMemorySize, SM_TOTAL);
  dim3 grid(H_, S_ / BM, B_);   // h fastest: heads sharing a mask tile co-resident
  attn_mma_kernel<<<grid, NT, SM_TOTAL>>>(q, k, v, mask, out_o, out_s);
}